// round 1
// baseline (speedup 1.0000x reference)
#include <cuda_runtime.h>
#include <cstdint>

#define DIM   256
#define HIST  200
#define NPASS 7      // ceil(200/32) row passes of 32
#define EPSF  1e-12f

// Batch-invariant precomputed C = P @ W2 + bias  [HIST, DIM]
__device__ float g_C[HIST * DIM];

// ---------------------------------------------------------------------------
// Kernel A: C[h][d] = sum_k P[h][k] * W2[k][d] + bias[h][d]
// ---------------------------------------------------------------------------
__global__ void compute_C_kernel(const float* __restrict__ P,
                                 const float* __restrict__ W2,
                                 const float* __restrict__ bias) {
    __shared__ float sP[DIM];
    const int h = blockIdx.x;
    const int d = threadIdx.x;
    sP[d] = P[h * DIM + d];
    __syncthreads();
    float acc = 0.f;
    #pragma unroll 16
    for (int k = 0; k < DIM; ++k)
        acc = fmaf(sP[k], W2[k * DIM + d], acc);
    g_C[h * DIM + d] = acc + bias[h * DIM + d];
}

__device__ __forceinline__ float tanh_approx(float x) {
    float y;
    asm("tanh.approx.f32 %0, %1;" : "=f"(y) : "f"(x));
    return y;
}

// ---------------------------------------------------------------------------
// Kernel B: one CTA per batch element.
//   Streaming over history rows in passes of 32:
//     gather+max_norm rows -> smem tile sA
//     acc[r][c] = sA[row] @ W1 columns (TM=8 x TN=4 register tile per thread)
//     epilogue: t = tanh(acc + C), e = exp(t), den += e, num += e*hist
//   Then l = num/den + a, and score = || norm(u) + norm(l) - norm(v) ||_2.
// ---------------------------------------------------------------------------
__global__ __launch_bounds__(256, 2)
void geo_main_kernel(const int* __restrict__ batch_u,
                     const int* __restrict__ batch_v,
                     const int* __restrict__ batch_history,
                     const float* __restrict__ user_emb,
                     const float* __restrict__ venue_emb,
                     const float* __restrict__ W1,
                     const float* __restrict__ a_ptr,
                     float* __restrict__ out) {
    __shared__ __align__(16) float sA[32][DIM];   // 32 KB: normalized hist rows
    __shared__ float sDen[4][DIM];                // per-rowgroup partial den
    __shared__ float sNum[4][DIM];                // per-rowgroup partial num
    __shared__ float sL[DIM];                     // l vector
    __shared__ float sred[3][8];
    __shared__ float sbc[3];

    const int b    = blockIdx.x;
    const int tid  = threadIdx.x;
    const int lane = tid & 31;
    const int warp = tid >> 5;
    const int cg   = tid & 63;        // column group: owns cols d0..d0+3
    const int rg   = tid >> 6;        // row group: owns rows rg*8..rg*8+7 of a pass
    const int d0   = cg * 4;

    float den[4] = {0.f, 0.f, 0.f, 0.f};
    float num[4] = {0.f, 0.f, 0.f, 0.f};

    for (int pass = 0; pass < NPASS; ++pass) {
        __syncthreads();   // previous pass's epilogue reads of sA done

        // ---- gather + max_norm 32 history rows into sA (warp w -> 4 rows) ----
        #pragma unroll
        for (int rr = 0; rr < 4; ++rr) {
            const int lr  = warp * 4 + rr;
            const int row = pass * 32 + lr;
            float v[8];
            if (row < HIST) {
                const int idx = batch_history[b * HIST + row];
                const float4* src =
                    reinterpret_cast<const float4*>(venue_emb + (size_t)idx * DIM);
                float4 x0 = src[lane * 2 + 0];
                float4 x1 = src[lane * 2 + 1];
                v[0]=x0.x; v[1]=x0.y; v[2]=x0.z; v[3]=x0.w;
                v[4]=x1.x; v[5]=x1.y; v[6]=x1.z; v[7]=x1.w;
            } else {
                #pragma unroll
                for (int j = 0; j < 8; ++j) v[j] = 0.f;
            }
            float ss = 0.f;
            #pragma unroll
            for (int j = 0; j < 8; ++j) ss = fmaf(v[j], v[j], ss);
            #pragma unroll
            for (int o = 16; o > 0; o >>= 1)
                ss += __shfl_xor_sync(0xffffffffu, ss, o);
            const float n  = sqrtf(ss);
            const float sc = fminf(1.0f, 1.0f / fmaxf(n, EPSF));  // torch max_norm=1
            float4* dst = reinterpret_cast<float4*>(&sA[lr][lane * 8]);
            dst[0] = make_float4(v[0]*sc, v[1]*sc, v[2]*sc, v[3]*sc);
            dst[1] = make_float4(v[4]*sc, v[5]*sc, v[6]*sc, v[7]*sc);
        }
        __syncthreads();

        // ---- register-tiled GEMM: acc[r][c] = sum_k sA[rg*8+r][k]*W1[k][d0+c] ----
        float acc[8][4];
        #pragma unroll
        for (int r = 0; r < 8; ++r)
            #pragma unroll
            for (int c = 0; c < 4; ++c) acc[r][c] = 0.f;

        #pragma unroll 2
        for (int k = 0; k < DIM; k += 4) {
            float w[4][4];
            #pragma unroll
            for (int i = 0; i < 4; ++i) {
                float4 wv = *reinterpret_cast<const float4*>(W1 + (k + i) * DIM + d0);
                w[i][0] = wv.x; w[i][1] = wv.y; w[i][2] = wv.z; w[i][3] = wv.w;
            }
            #pragma unroll
            for (int r = 0; r < 8; ++r) {
                // broadcast LDS.128 (all lanes in warp share rg)
                float4 av = *reinterpret_cast<const float4*>(&sA[rg * 8 + r][k]);
                float am[4] = {av.x, av.y, av.z, av.w};
                #pragma unroll
                for (int i = 0; i < 4; ++i)
                    #pragma unroll
                    for (int c = 0; c < 4; ++c)
                        acc[r][c] = fmaf(am[i], w[i][c], acc[r][c]);
            }
        }

        // ---- streaming softmax epilogue ----
        #pragma unroll
        for (int r = 0; r < 8; ++r) {
            const int row = pass * 32 + rg * 8 + r;
            if (row < HIST) {
                float4 hv = *reinterpret_cast<const float4*>(&sA[rg * 8 + r][d0]);
                float4 cv = *reinterpret_cast<const float4*>(&g_C[row * DIM + d0]);
                float hm[4] = {hv.x, hv.y, hv.z, hv.w};
                float cm[4] = {cv.x, cv.y, cv.z, cv.w};
                #pragma unroll
                for (int c = 0; c < 4; ++c) {
                    float t = tanh_approx(acc[r][c] + cm[c]);
                    float e = __expf(t);       // t in [-1,1]: no max-subtraction needed
                    den[c] += e;
                    num[c] = fmaf(e, hm[c], num[c]);
                }
            }
        }
    }

    // ---- reduce den/num across the 4 row groups, form l ----
    __syncthreads();
    #pragma unroll
    for (int c = 0; c < 4; ++c) {
        sDen[rg][d0 + c] = den[c];
        sNum[rg][d0 + c] = num[c];
    }
    __syncthreads();
    {
        const float a_val = a_ptr[0];
        float dt = 0.f, nt = 0.f;
        #pragma unroll
        for (int g = 0; g < 4; ++g) { dt += sDen[g][tid]; nt += sNum[g][tid]; }
        sL[tid] = nt / dt + a_val;
    }
    __syncthreads();

    // ---- final TransE score.  l2norm(max_norm_lookup(x)) == l2norm(x). ----
    const float lv  = sL[tid];
    const float uvv = user_emb [(size_t)batch_u[b] * DIM + tid];
    const float vvv = venue_emb[(size_t)batch_v[b] * DIM + tid];
    float su = uvv * uvv, sv = vvv * vvv, sl = lv * lv;
    #pragma unroll
    for (int o = 16; o > 0; o >>= 1) {
        su += __shfl_xor_sync(0xffffffffu, su, o);
        sv += __shfl_xor_sync(0xffffffffu, sv, o);
        sl += __shfl_xor_sync(0xffffffffu, sl, o);
    }
    if (lane == 0) { sred[0][warp] = su; sred[1][warp] = sv; sred[2][warp] = sl; }
    __syncthreads();
    if (tid == 0) {
        float tu = 0.f, tv = 0.f, tl = 0.f;
        #pragma unroll
        for (int w = 0; w < 8; ++w) { tu += sred[0][w]; tv += sred[1][w]; tl += sred[2][w]; }
        sbc[0] = 1.f / fmaxf(sqrtf(tu), EPSF);
        sbc[1] = 1.f / fmaxf(sqrtf(tv), EPSF);
        sbc[2] = 1.f / fmaxf(sqrtf(tl), EPSF);
    }
    __syncthreads();
    float s   = uvv * sbc[0] + lv * sbc[2] - vvv * sbc[1];
    float ssq = s * s;
    #pragma unroll
    for (int o = 16; o > 0; o >>= 1)
        ssq += __shfl_xor_sync(0xffffffffu, ssq, o);
    if (lane == 0) sred[0][warp] = ssq;
    __syncthreads();
    if (tid == 0) {
        float t = 0.f;
        #pragma unroll
        for (int w = 0; w < 8; ++w) t += sred[0][w];
        out[b] = sqrtf(t);
    }
}

// ---------------------------------------------------------------------------
// Harness entry.  Input order (metadata): batch_u, batch_v, batch_history,
// batch_olc, batch_cluster_olc, user_emb, venue_emb, W1, W2, P, bias, a.
// batch_olc / batch_cluster_olc are unused in the reference forward.
// ---------------------------------------------------------------------------
extern "C" void kernel_launch(void* const* d_in, const int* in_sizes, int n_in,
                              void* d_out, int out_size) {
    const int*   batch_u       = (const int*)d_in[0];
    const int*   batch_v       = (const int*)d_in[1];
    const int*   batch_history = (const int*)d_in[2];
    const float* user_emb      = (const float*)d_in[5];
    const float* venue_emb     = (const float*)d_in[6];
    const float* W1            = (const float*)d_in[7];
    const float* W2            = (const float*)d_in[8];
    const float* P             = (const float*)d_in[9];
    const float* bias          = (const float*)d_in[10];
    const float* a             = (const float*)d_in[11];
    float* out = (float*)d_out;

    const int B = in_sizes[0];

    compute_C_kernel<<<HIST, DIM>>>(P, W2, bias);
    geo_main_kernel<<<B, 256>>>(batch_u, batch_v, batch_history,
                                user_emb, venue_emb, W1, a, out);
}

// round 3
// speedup vs baseline: 2.7185x; 2.7185x over previous
#include <cuda_runtime.h>
#include <cuda_bf16.h>
#include <cstdint>

#define DIM   256
#define HIST  200
#define VROWS 100000
#define EPSF  1e-12f

#define MPAD  224            // 7 compute warps * 32 rows
#define ROWB  528            // smem row stride bytes: (256+8) bf16
#define NCHUNK 64            // N tile per pass

// ---------------- persistent device scratch ----------------
__device__ __nv_bfloat16 g_vnorm[(size_t)VROWS * DIM];  // max-norm venue rows, bf16
__device__ __nv_bfloat16 g_Bt[DIM * DIM];               // W1^T  (Bt[n][k] = W1[k][n])
__device__ float         g_C[HIST * DIM];               // P@W2 + bias

// ---------------- helpers ----------------
__device__ __forceinline__ uint32_t smem_u32(const void* p) {
    uint32_t a;
    asm("{ .reg .u64 t; cvta.to.shared.u64 t, %1; cvt.u32.u64 %0, t; }" : "=r"(a) : "l"(p));
    return a;
}
__device__ __forceinline__ float tanh_fast(float x) {
    float y; asm("tanh.approx.f32 %0, %1;" : "=f"(y) : "f"(x)); return y;
}
__device__ __forceinline__ void ldsm_x4(uint32_t* r, uint32_t addr) {
    asm volatile("ldmatrix.sync.aligned.m8n8.x4.shared.b16 {%0,%1,%2,%3}, [%4];"
                 : "=r"(r[0]), "=r"(r[1]), "=r"(r[2]), "=r"(r[3]) : "r"(addr));
}
__device__ __forceinline__ void mma_bf16(float* d, const uint32_t* a,
                                         uint32_t b0, uint32_t b1) {
    asm volatile(
        "mma.sync.aligned.m16n8k16.row.col.f32.bf16.bf16.f32 "
        "{%0,%1,%2,%3}, {%4,%5,%6,%7}, {%8,%9}, {%0,%1,%2,%3};"
        : "+f"(d[0]), "+f"(d[1]), "+f"(d[2]), "+f"(d[3])
        : "r"(a[0]), "r"(a[1]), "r"(a[2]), "r"(a[3]), "r"(b0), "r"(b1));
}

// ---------------- precompute kernels ----------------
__global__ void normalize_venue_kernel(const float* __restrict__ venue, int rows) {
    const int row  = blockIdx.x * 8 + (threadIdx.x >> 5);
    const int lane = threadIdx.x & 31;
    if (row >= rows) return;
    const float4* src = reinterpret_cast<const float4*>(venue + (size_t)row * DIM) + lane * 2;
    float4 x0 = src[0], x1 = src[1];
    float ss = x0.x*x0.x + x0.y*x0.y + x0.z*x0.z + x0.w*x0.w
             + x1.x*x1.x + x1.y*x1.y + x1.z*x1.z + x1.w*x1.w;
    #pragma unroll
    for (int o = 16; o > 0; o >>= 1) ss += __shfl_xor_sync(0xffffffffu, ss, o);
    const float sc = fminf(1.0f, 1.0f / fmaxf(sqrtf(ss), EPSF));   // torch max_norm=1
    __nv_bfloat162 b0 = __floats2bfloat162_rn(x0.x*sc, x0.y*sc);
    __nv_bfloat162 b1 = __floats2bfloat162_rn(x0.z*sc, x0.w*sc);
    __nv_bfloat162 b2 = __floats2bfloat162_rn(x1.x*sc, x1.y*sc);
    __nv_bfloat162 b3 = __floats2bfloat162_rn(x1.z*sc, x1.w*sc);
    uint4 o;
    o.x = *reinterpret_cast<uint32_t*>(&b0); o.y = *reinterpret_cast<uint32_t*>(&b1);
    o.z = *reinterpret_cast<uint32_t*>(&b2); o.w = *reinterpret_cast<uint32_t*>(&b3);
    reinterpret_cast<uint4*>(g_vnorm + (size_t)row * DIM)[lane] = o;
}

__global__ void build_Bt_kernel(const float* __restrict__ W1) {
    const int n = blockIdx.x, k = threadIdx.x;
    g_Bt[n * DIM + k] = __float2bfloat16(W1[k * DIM + n]);
}

__global__ void compute_C_kernel(const float* __restrict__ P,
                                 const float* __restrict__ W2,
                                 const float* __restrict__ bias) {
    __shared__ float sP[DIM];
    const int h = blockIdx.x, d = threadIdx.x;
    sP[d] = P[h * DIM + d];
    __syncthreads();
    float acc = 0.f;
    #pragma unroll 16
    for (int k = 0; k < DIM; ++k) acc = fmaf(sP[k], W2[k * DIM + d], acc);
    g_C[h * DIM + d] = acc + bias[h * DIM + d];
}

// ---------------- main kernel: one CTA per batch element ----------------
// smem: A [224][264] bf16 @0 (118272B), B chunk [64][264] bf16 @118272 (33792B),
//       sDen @152064 (1024B), sNum @153088 (1024B)  -> 154112B total
#define SM_A    0
#define SM_B    118272
#define SM_DEN  152064
#define SM_NUM  153088
#define SM_BYTES 154112

__global__ __launch_bounds__(256, 1)
void geo_main_kernel(const int* __restrict__ batch_u,
                     const int* __restrict__ batch_v,
                     const int* __restrict__ batch_history,
                     const float* __restrict__ user_emb,
                     const float* __restrict__ venue_emb,
                     const float* __restrict__ a_ptr,
                     float* __restrict__ out) {
    extern __shared__ __align__(16) char sm[];
    __shared__ float sred[24];
    __shared__ float sbc[3];

    const int b = blockIdx.x, tid = threadIdx.x, lane = tid & 31, warp = tid >> 5;
    float* sDen = reinterpret_cast<float*>(sm + SM_DEN);
    float* sNum = reinterpret_cast<float*>(sm + SM_NUM);
    sDen[tid] = 0.f; sNum[tid] = 0.f;

    // ---- gather 200 normalized bf16 history rows (+ zero pad rows) ----
    for (int r = warp; r < MPAD; r += 8) {
        uint4 data = make_uint4(0, 0, 0, 0);
        if (r < HIST) {
            const int idx = batch_history[b * HIST + r];
            data = reinterpret_cast<const uint4*>(g_vnorm + (size_t)idx * DIM)[lane];
        }
        *reinterpret_cast<uint4*>(sm + SM_A + r * ROWB + lane * 16) = data;
    }
    __syncthreads();

    const uint32_t smA = smem_u32(sm + SM_A);
    const uint32_t smB = smem_u32(sm + SM_B);
    const int qr = lane >> 2, qc = lane & 3;

    // ldmatrix lane address bases (k0 = 0)
    const uint32_t aAddr0 = smA + (uint32_t)((warp * 32 + (lane & 15)) * ROWB + (lane >> 4) * 16);
    const uint32_t aAddr1 = aAddr0 + 16 * ROWB;
    const uint32_t bAddrB = smB + (uint32_t)(((lane & 7) + ((lane >> 4) & 1) * 8) * ROWB
                                             + ((lane >> 3) & 1) * 16);

    #pragma unroll 1
    for (int chunk = 0; chunk < 4; ++chunk) {
        // ---- copy B chunk: Bt rows [chunk*64 .. +63], all 256 k ----
        {
            const uint4* src = reinterpret_cast<const uint4*>(g_Bt + chunk * NCHUNK * DIM);
            #pragma unroll
            for (int i = tid; i < 2048; i += 256) {
                const int row = i >> 5, j = i & 31;
                *reinterpret_cast<uint4*>(sm + SM_B + row * ROWB + j * 16) = src[row * 32 + j];
            }
        }
        __syncthreads();

        if (warp < 7) {
            // ---- mma mainloop: 32 rows x 64 cols per warp ----
            float acc[2][8][4];
            #pragma unroll
            for (int mt = 0; mt < 2; ++mt)
                #pragma unroll
                for (int nt = 0; nt < 8; ++nt)
                    #pragma unroll
                    for (int i = 0; i < 4; ++i) acc[mt][nt][i] = 0.f;

            #pragma unroll 4
            for (int ks = 0; ks < 16; ++ks) {
                uint32_t af[2][4], bf[4][4];
                ldsm_x4(af[0], aAddr0 + ks * 32);
                ldsm_x4(af[1], aAddr1 + ks * 32);
                #pragma unroll
                for (int p = 0; p < 4; ++p)
                    ldsm_x4(bf[p], bAddrB + p * 16 * ROWB + ks * 32);
                #pragma unroll
                for (int mt = 0; mt < 2; ++mt)
                    #pragma unroll
                    for (int nt = 0; nt < 8; ++nt)
                        mma_bf16(acc[mt][nt], af[mt],
                                 bf[nt >> 1][(nt & 1) * 2], bf[nt >> 1][(nt & 1) * 2 + 1]);
            }

            // ---- fused epilogue: tanh -> exp -> streaming softmax partials ----
            #pragma unroll
            for (int nt = 0; nt < 8; ++nt) {
                const int gcol = chunk * NCHUNK + nt * 8 + 2 * qc;
                float d0 = 0.f, d1 = 0.f, s0 = 0.f, s1 = 0.f;
                #pragma unroll
                for (int mt = 0; mt < 2; ++mt) {
                    #pragma unroll
                    for (int half = 0; half < 2; ++half) {
                        const int row = warp * 32 + mt * 16 + qr + half * 8;
                        const bool act = (row < HIST);
                        const int crow = act ? row : 0;
                        const float2 cc = *reinterpret_cast<const float2*>(
                            g_C + (size_t)crow * DIM + gcol);
                        const uint32_t hh = *reinterpret_cast<const uint32_t*>(
                            sm + SM_A + row * ROWB + gcol * 2);
                        const float2 hv = __bfloat1622float2(
                            *reinterpret_cast<const __nv_bfloat162*>(&hh));
                        const float x0 = acc[mt][nt][half * 2 + 0] + cc.x;
                        const float x1 = acc[mt][nt][half * 2 + 1] + cc.y;
                        const float e0 = act ? __expf(tanh_fast(x0)) : 0.f;
                        const float e1 = act ? __expf(tanh_fast(x1)) : 0.f;
                        d0 += e0; d1 += e1;
                        s0 = fmaf(e0, hv.x, s0); s1 = fmaf(e1, hv.y, s1);
                    }
                }
                #pragma unroll
                for (int off = 4; off < 32; off <<= 1) {
                    d0 += __shfl_xor_sync(0xffffffffu, d0, off);
                    d1 += __shfl_xor_sync(0xffffffffu, d1, off);
                    s0 += __shfl_xor_sync(0xffffffffu, s0, off);
                    s1 += __shfl_xor_sync(0xffffffffu, s1, off);
                }
                if (lane < 4) {                    // lane == qc for lanes 0-3
                    atomicAdd(&sDen[gcol], d0);
                    atomicAdd(&sDen[gcol + 1], d1);
                    atomicAdd(&sNum[gcol], s0);
                    atomicAdd(&sNum[gcol + 1], s1);
                }
            }
        }
        __syncthreads();   // B chunk fully consumed + partials written
    }

    // ---- l = num/den + a; score = || l2n(u) + l2n(l) - l2n(v) || ----
    const float a_val = a_ptr[0];
    const float lv  = sNum[tid] / sDen[tid] + a_val;
    const float uvv = user_emb [(size_t)batch_u[b] * DIM + tid];
    const float vvv = venue_emb[(size_t)batch_v[b] * DIM + tid];
    float su = uvv * uvv, sv = vvv * vvv, sl = lv * lv;
    #pragma unroll
    for (int o = 16; o > 0; o >>= 1) {
        su += __shfl_xor_sync(0xffffffffu, su, o);
        sv += __shfl_xor_sync(0xffffffffu, sv, o);
        sl += __shfl_xor_sync(0xffffffffu, sl, o);
    }
    if (lane == 0) { sred[warp] = su; sred[8 + warp] = sv; sred[16 + warp] = sl; }
    __syncthreads();
    if (tid == 0) {
        float tu = 0.f, tv = 0.f, tl = 0.f;
        #pragma unroll
        for (int w = 0; w < 8; ++w) { tu += sred[w]; tv += sred[8 + w]; tl += sred[16 + w]; }
        sbc[0] = 1.f / fmaxf(sqrtf(tu), EPSF);
        sbc[1] = 1.f / fmaxf(sqrtf(tv), EPSF);
        sbc[2] = 1.f / fmaxf(sqrtf(tl), EPSF);
    }
    __syncthreads();
    float s = uvv * sbc[0] + lv * sbc[2] - vvv * sbc[1];
    float ssq = s * s;
    #pragma unroll
    for (int o = 16; o > 0; o >>= 1) ssq += __shfl_xor_sync(0xffffffffu, ssq, o);
    if (lane == 0) sred[warp] = ssq;
    __syncthreads();
    if (tid == 0) {
        float tot = 0.f;
        #pragma unroll
        for (int w = 0; w < 8; ++w) tot += sred[w];
        out[b] = sqrtf(tot);
    }
}

// ---------------- harness entry ----------------
extern "C" void kernel_launch(void* const* d_in, const int* in_sizes, int n_in,
                              void* d_out, int out_size) {
    const int*   batch_u       = (const int*)d_in[0];
    const int*   batch_v       = (const int*)d_in[1];
    const int*   batch_history = (const int*)d_in[2];
    const float* user_emb      = (const float*)d_in[5];
    const float* venue_emb     = (const float*)d_in[6];
    const float* W1            = (const float*)d_in[7];
    const float* W2            = (const float*)d_in[8];
    const float* P             = (const float*)d_in[9];
    const float* bias          = (const float*)d_in[10];
    const float* a             = (const float*)d_in[11];
    float* out = (float*)d_out;

    const int B = in_sizes[0];
    int rows = in_sizes[6] / DIM;
    if (rows > VROWS) rows = VROWS;

    cudaFuncSetAttribute(geo_main_kernel,
                         cudaFuncAttributeMaxDynamicSharedMemorySize, SM_BYTES);

    normalize_venue_kernel<<<(rows + 7) / 8, 256>>>(venue_emb, rows);
    build_Bt_kernel<<<DIM, DIM>>>(W1);
    compute_C_kernel<<<HIST, DIM>>>(P, W2, bias);
    geo_main_kernel<<<B, 256, SM_BYTES>>>(batch_u, batch_v, batch_history,
                                          user_emb, venue_emb, a, out);
}

// round 4
// speedup vs baseline: 2.7510x; 1.0120x over previous
#include <cuda_runtime.h>
#include <cuda_bf16.h>
#include <cstdint>

#define DIM   256
#define HIST  200
#define VROWS 100000
#define EPSF  1e-12f

#define MPAD   256           // 16 warps * 16 rows (rows 200..255 zero)
#define ROWB   528           // smem row stride bytes: (256+8) bf16
#define NCHUNK 64            // N tile per pass

// ---------------- persistent device scratch ----------------
__device__ __nv_bfloat16 g_vnorm[(size_t)VROWS * DIM];  // max-norm venue rows, bf16
__device__ __nv_bfloat16 g_Bt[DIM * DIM];               // W1^T  (Bt[n][k] = W1[k][n])
__device__ float         g_C[HIST * DIM];               // P@W2 + bias

// ---------------- helpers ----------------
__device__ __forceinline__ uint32_t smem_u32(const void* p) {
    uint32_t a;
    asm("{ .reg .u64 t; cvta.to.shared.u64 t, %1; cvt.u32.u64 %0, t; }" : "=r"(a) : "l"(p));
    return a;
}
__device__ __forceinline__ float tanh_fast(float x) {
    float y; asm("tanh.approx.f32 %0, %1;" : "=f"(y) : "f"(x)); return y;
}
__device__ __forceinline__ void ldsm_x4(uint32_t* r, uint32_t addr) {
    asm volatile("ldmatrix.sync.aligned.m8n8.x4.shared.b16 {%0,%1,%2,%3}, [%4];"
                 : "=r"(r[0]), "=r"(r[1]), "=r"(r[2]), "=r"(r[3]) : "r"(addr));
}
__device__ __forceinline__ void mma_bf16(float* d, const uint32_t* a,
                                         uint32_t b0, uint32_t b1) {
    asm volatile(
        "mma.sync.aligned.m16n8k16.row.col.f32.bf16.bf16.f32 "
        "{%0,%1,%2,%3}, {%4,%5,%6,%7}, {%8,%9}, {%0,%1,%2,%3};"
        : "+f"(d[0]), "+f"(d[1]), "+f"(d[2]), "+f"(d[3])
        : "r"(a[0]), "r"(a[1]), "r"(a[2]), "r"(a[3]), "r"(b0), "r"(b1));
}
__device__ __forceinline__ void cp16(uint32_t dst, const void* src) {
    asm volatile("cp.async.cg.shared.global [%0], [%1], 16;" :: "r"(dst), "l"(src));
}
__device__ __forceinline__ void cp_commit() {
    asm volatile("cp.async.commit_group;" ::: "memory");
}
__device__ __forceinline__ void cp_wait0() {
    asm volatile("cp.async.wait_group 0;" ::: "memory");
}

// ---------------- precompute kernels ----------------
__global__ void normalize_venue_kernel(const float* __restrict__ venue, int rows) {
    const int row  = blockIdx.x * 8 + (threadIdx.x >> 5);
    const int lane = threadIdx.x & 31;
    if (row >= rows) return;
    const float4* src = reinterpret_cast<const float4*>(venue + (size_t)row * DIM) + lane * 2;
    float4 x0 = src[0], x1 = src[1];
    float ss = x0.x*x0.x + x0.y*x0.y + x0.z*x0.z + x0.w*x0.w
             + x1.x*x1.x + x1.y*x1.y + x1.z*x1.z + x1.w*x1.w;
    #pragma unroll
    for (int o = 16; o > 0; o >>= 1) ss += __shfl_xor_sync(0xffffffffu, ss, o);
    const float sc = fminf(1.0f, 1.0f / fmaxf(sqrtf(ss), EPSF));   // torch max_norm=1
    __nv_bfloat162 b0 = __floats2bfloat162_rn(x0.x*sc, x0.y*sc);
    __nv_bfloat162 b1 = __floats2bfloat162_rn(x0.z*sc, x0.w*sc);
    __nv_bfloat162 b2 = __floats2bfloat162_rn(x1.x*sc, x1.y*sc);
    __nv_bfloat162 b3 = __floats2bfloat162_rn(x1.z*sc, x1.w*sc);
    uint4 o;
    o.x = *reinterpret_cast<uint32_t*>(&b0); o.y = *reinterpret_cast<uint32_t*>(&b1);
    o.z = *reinterpret_cast<uint32_t*>(&b2); o.w = *reinterpret_cast<uint32_t*>(&b3);
    reinterpret_cast<uint4*>(g_vnorm + (size_t)row * DIM)[lane] = o;
}

__global__ void build_Bt_kernel(const float* __restrict__ W1) {
    const int n = blockIdx.x, k = threadIdx.x;
    g_Bt[n * DIM + k] = __float2bfloat16(W1[k * DIM + n]);
}

__global__ void compute_C_kernel(const float* __restrict__ P,
                                 const float* __restrict__ W2,
                                 const float* __restrict__ bias) {
    __shared__ float sP[DIM];
    const int h = blockIdx.x, d = threadIdx.x;
    sP[d] = P[h * DIM + d];
    __syncthreads();
    float acc = 0.f;
    #pragma unroll 16
    for (int k = 0; k < DIM; ++k) acc = fmaf(sP[k], W2[k * DIM + d], acc);
    g_C[h * DIM + d] = acc + bias[h * DIM + d];
}

// ---------------- main kernel: one CTA per batch element, 512 threads ----------------
// smem: A [256][264] bf16 (135168B), B0/B1 [64][264] bf16 (33792B each),
//       sDen (1024B), sNum (1024B)  -> 204800B total
#define SM_A    0
#define SM_B0   135168
#define SM_B1   168960
#define SM_DEN  202752
#define SM_NUM  203776
#define SM_BYTES 204800

__global__ __launch_bounds__(512, 1)
void geo_main_kernel(const int* __restrict__ batch_u,
                     const int* __restrict__ batch_v,
                     const int* __restrict__ batch_history,
                     const float* __restrict__ user_emb,
                     const float* __restrict__ venue_emb,
                     const float* __restrict__ a_ptr,
                     float* __restrict__ out) {
    extern __shared__ __align__(16) char sm[];
    __shared__ float sred[24];
    __shared__ float sbc[3];

    const int b = blockIdx.x, tid = threadIdx.x, lane = tid & 31, warp = tid >> 5;
    float* sDen = reinterpret_cast<float*>(sm + SM_DEN);
    float* sNum = reinterpret_cast<float*>(sm + SM_NUM);
    if (tid < 256) { sDen[tid] = 0.f; sNum[tid] = 0.f; }

    const uint32_t smA  = smem_u32(sm + SM_A);
    const uint32_t smB[2] = { smem_u32(sm + SM_B0), smem_u32(sm + SM_B1) };

    // ---- B chunk 0 async copy (overlaps A gather) ----
    {
        const char* src = reinterpret_cast<const char*>(g_Bt);   // rows 0..63
        #pragma unroll
        for (int s = 0; s < 4; ++s) {
            const int i = tid + s * 512;        // 0..2047
            const int row = i >> 5, j = i & 31;
            cp16(smB[0] + row * ROWB + j * 16, src + row * 512 + j * 16);
        }
    }
    // ---- A gather: warp w -> rows w*16..w*16+15 (cp.async), zeros for pad rows ----
    {
        #pragma unroll
        for (int i = 0; i < 16; ++i) {
            const int r = warp * 16 + i;
            if (r < HIST) {
                const int idx = batch_history[b * HIST + r];
                cp16(smA + r * ROWB + lane * 16,
                     reinterpret_cast<const char*>(g_vnorm + (size_t)idx * DIM) + lane * 16);
            } else {
                *reinterpret_cast<uint4*>(sm + SM_A + r * ROWB + lane * 16) =
                    make_uint4(0, 0, 0, 0);
            }
        }
    }
    cp_commit();
    cp_wait0();
    __syncthreads();

    const int qr = lane >> 2, qc = lane & 3;
    const uint32_t aAddr = smA + (uint32_t)((warp * 16 + (lane & 15)) * ROWB + (lane >> 4) * 16);
    const uint32_t bOff  = (uint32_t)(((lane & 7) + ((lane >> 4) & 1) * 8) * ROWB
                                      + ((lane >> 3) & 1) * 16);

    #pragma unroll 1
    for (int chunk = 0; chunk < 4; ++chunk) {
        // ---- prefetch next B chunk (async) ----
        if (chunk < 3) {
            const char* src = reinterpret_cast<const char*>(g_Bt + (chunk + 1) * NCHUNK * DIM);
            const uint32_t dstB = smB[(chunk + 1) & 1];
            #pragma unroll
            for (int s = 0; s < 4; ++s) {
                const int i = tid + s * 512;
                const int row = i >> 5, j = i & 31;
                cp16(dstB + row * ROWB + j * 16, src + row * 512 + j * 16);
            }
            cp_commit();
        }

        // ---- mma mainloop: 16 rows x 64 cols per warp ----
        const uint32_t bAddr = smB[chunk & 1] + bOff;
        float acc[8][4];
        #pragma unroll
        for (int nt = 0; nt < 8; ++nt)
            #pragma unroll
            for (int i = 0; i < 4; ++i) acc[nt][i] = 0.f;

        #pragma unroll 4
        for (int ks = 0; ks < 16; ++ks) {
            uint32_t af[4], bf[4][4];
            ldsm_x4(af, aAddr + ks * 32);
            #pragma unroll
            for (int p = 0; p < 4; ++p)
                ldsm_x4(bf[p], bAddr + p * 16 * ROWB + ks * 32);
            #pragma unroll
            for (int nt = 0; nt < 8; ++nt)
                mma_bf16(acc[nt], af, bf[nt >> 1][(nt & 1) * 2], bf[nt >> 1][(nt & 1) * 2 + 1]);
        }

        // ---- fused epilogue: tanh -> exp -> streaming softmax partials ----
        #pragma unroll
        for (int nt = 0; nt < 8; ++nt) {
            const int gcol = chunk * NCHUNK + nt * 8 + 2 * qc;
            float d0 = 0.f, d1 = 0.f, s0 = 0.f, s1 = 0.f;
            #pragma unroll
            for (int half = 0; half < 2; ++half) {
                const int row = warp * 16 + qr + half * 8;
                const bool act = (row < HIST);
                const int crow = act ? row : 0;
                const float2 cc = *reinterpret_cast<const float2*>(
                    g_C + (size_t)crow * DIM + gcol);
                const uint32_t hh = *reinterpret_cast<const uint32_t*>(
                    sm + SM_A + row * ROWB + gcol * 2);
                const float2 hv = __bfloat1622float2(
                    *reinterpret_cast<const __nv_bfloat162*>(&hh));
                const float x0 = acc[nt][half * 2 + 0] + cc.x;
                const float x1 = acc[nt][half * 2 + 1] + cc.y;
                const float e0 = act ? __expf(tanh_fast(x0)) : 0.f;
                const float e1 = act ? __expf(tanh_fast(x1)) : 0.f;
                d0 += e0; d1 += e1;
                s0 = fmaf(e0, hv.x, s0); s1 = fmaf(e1, hv.y, s1);
            }
            #pragma unroll
            for (int off = 4; off < 32; off <<= 1) {
                d0 += __shfl_xor_sync(0xffffffffu, d0, off);
                d1 += __shfl_xor_sync(0xffffffffu, d1, off);
                s0 += __shfl_xor_sync(0xffffffffu, s0, off);
                s1 += __shfl_xor_sync(0xffffffffu, s1, off);
            }
            if (lane < 4) {                    // lane == qc for lanes 0-3
                atomicAdd(&sDen[gcol], d0);
                atomicAdd(&sDen[gcol + 1], d1);
                atomicAdd(&sNum[gcol], s0);
                atomicAdd(&sNum[gcol + 1], s1);
            }
        }

        cp_wait0();
        __syncthreads();   // B[chunk] consumed; B[chunk+1] landed; partials visible
    }

    // ---- l = num/den + a; score = || l2n(u) + l2n(l) - l2n(v) || ----
    float lv = 0.f, uvv = 0.f, vvv = 0.f;
    if (tid < 256) {
        const float a_val = a_ptr[0];
        lv  = sNum[tid] / sDen[tid] + a_val;
        uvv = user_emb [(size_t)batch_u[b] * DIM + tid];
        vvv = venue_emb[(size_t)batch_v[b] * DIM + tid];
        float su = uvv * uvv, sv = vvv * vvv, sl = lv * lv;
        #pragma unroll
        for (int o = 16; o > 0; o >>= 1) {
            su += __shfl_xor_sync(0xffffffffu, su, o);
            sv += __shfl_xor_sync(0xffffffffu, sv, o);
            sl += __shfl_xor_sync(0xffffffffu, sl, o);
        }
        if (lane == 0) { sred[warp] = su; sred[8 + warp] = sv; sred[16 + warp] = sl; }
    }
    __syncthreads();
    if (tid == 0) {
        float tu = 0.f, tv = 0.f, tl = 0.f;
        #pragma unroll
        for (int w = 0; w < 8; ++w) { tu += sred[w]; tv += sred[8 + w]; tl += sred[16 + w]; }
        sbc[0] = 1.f / fmaxf(sqrtf(tu), EPSF);
        sbc[1] = 1.f / fmaxf(sqrtf(tv), EPSF);
        sbc[2] = 1.f / fmaxf(sqrtf(tl), EPSF);
    }
    __syncthreads();
    if (tid < 256) {
        float s = uvv * sbc[0] + lv * sbc[2] - vvv * sbc[1];
        float ssq = s * s;
        #pragma unroll
        for (int o = 16; o > 0; o >>= 1) ssq += __shfl_xor_sync(0xffffffffu, ssq, o);
        if (lane == 0) sred[warp] = ssq;
    }
    __syncthreads();
    if (tid == 0) {
        float tot = 0.f;
        #pragma unroll
        for (int w = 0; w < 8; ++w) tot += sred[w];
        out[b] = sqrtf(tot);
    }
}

// ---------------- harness entry ----------------
extern "C" void kernel_launch(void* const* d_in, const int* in_sizes, int n_in,
                              void* d_out, int out_size) {
    const int*   batch_u       = (const int*)d_in[0];
    const int*   batch_v       = (const int*)d_in[1];
    const int*   batch_history = (const int*)d_in[2];
    const float* user_emb      = (const float*)d_in[5];
    const float* venue_emb     = (const float*)d_in[6];
    const float* W1            = (const float*)d_in[7];
    const float* W2            = (const float*)d_in[8];
    const float* P             = (const float*)d_in[9];
    const float* bias          = (const float*)d_in[10];
    const float* a             = (const float*)d_in[11];
    float* out = (float*)d_out;

    const int B = in_sizes[0];
    int rows = in_sizes[6] / DIM;
    if (rows > VROWS) rows = VROWS;

    cudaFuncSetAttribute(geo_main_kernel,
                         cudaFuncAttributeMaxDynamicSharedMemorySize, SM_BYTES);

    normalize_venue_kernel<<<(rows + 7) / 8, 256>>>(venue_emb, rows);
    build_Bt_kernel<<<DIM, DIM>>>(W1);
    compute_C_kernel<<<HIST, DIM>>>(P, W2, bias);
    geo_main_kernel<<<B, 512, SM_BYTES>>>(batch_u, batch_v, batch_history,
                                          user_emb, venue_emb, a, out);
}

// round 5
// speedup vs baseline: 6.8408x; 2.4867x over previous
#include <cuda_runtime.h>
#include <cuda_bf16.h>
#include <cstdint>

#define DIM   256
#define HIST  200
#define VROWS 100000
#define EPSF  1e-12f
#define ROWB  528            // smem row stride bytes: (256+8) bf16

// ---------------- persistent device scratch ----------------
__device__ __nv_bfloat16 g_vnorm[(size_t)VROWS * DIM];  // max-norm venue rows, bf16
__device__ __nv_bfloat16 g_Bt[DIM * DIM];               // W1^T  (Bt[n][k] = W1[k][n])
__device__ float         g_C[HIST * DIM];               // P@W2 + bias
__device__ float         g_T[(size_t)VROWS * DIM];      // vnorm @ W1  (fp32, 102.4MB)

// ---------------- helpers ----------------
__device__ __forceinline__ uint32_t smem_u32(const void* p) {
    uint32_t a;
    asm("{ .reg .u64 t; cvta.to.shared.u64 t, %1; cvt.u32.u64 %0, t; }" : "=r"(a) : "l"(p));
    return a;
}
__device__ __forceinline__ float tanh_fast(float x) {
    float y; asm("tanh.approx.f32 %0, %1;" : "=f"(y) : "f"(x)); return y;
}
__device__ __forceinline__ void ldsm_x4(uint32_t* r, uint32_t addr) {
    asm volatile("ldmatrix.sync.aligned.m8n8.x4.shared.b16 {%0,%1,%2,%3}, [%4];"
                 : "=r"(r[0]), "=r"(r[1]), "=r"(r[2]), "=r"(r[3]) : "r"(addr));
}
__device__ __forceinline__ void mma_bf16(float* d, const uint32_t* a,
                                         uint32_t b0, uint32_t b1) {
    asm volatile(
        "mma.sync.aligned.m16n8k16.row.col.f32.bf16.bf16.f32 "
        "{%0,%1,%2,%3}, {%4,%5,%6,%7}, {%8,%9}, {%0,%1,%2,%3};"
        : "+f"(d[0]), "+f"(d[1]), "+f"(d[2]), "+f"(d[3])
        : "r"(a[0]), "r"(a[1]), "r"(a[2]), "r"(a[3]), "r"(b0), "r"(b1));
}
__device__ __forceinline__ void cp16(uint32_t dst, const void* src) {
    asm volatile("cp.async.cg.shared.global [%0], [%1], 16;" :: "r"(dst), "l"(src));
}
__device__ __forceinline__ void cp_commit() { asm volatile("cp.async.commit_group;" ::: "memory"); }
__device__ __forceinline__ void cp_wait0()  { asm volatile("cp.async.wait_group 0;" ::: "memory"); }

// ---------------- small precompute kernels ----------------
__global__ void build_Bt_kernel(const float* __restrict__ W1) {
    const int n = blockIdx.x, k = threadIdx.x;
    g_Bt[n * DIM + k] = __float2bfloat16(W1[k * DIM + n]);
}

__global__ void compute_C_kernel(const float* __restrict__ P,
                                 const float* __restrict__ W2,
                                 const float* __restrict__ bias) {
    __shared__ float sP[DIM];
    const int h = blockIdx.x, d = threadIdx.x;
    sP[d] = P[h * DIM + d];
    __syncthreads();
    float acc = 0.f;
    #pragma unroll 16
    for (int k = 0; k < DIM; ++k) acc = fmaf(sP[k], W2[k * DIM + d], acc);
    g_C[h * DIM + d] = acc + bias[h * DIM + d];
}

// ---------------- T = max_norm(venue) @ W1, fused normalize ----------------
// grid = ceil(rows/128), 256 threads, smem A 67584 + B 33792 = 101376 -> occ 2
#define GSM_A 0
#define GSM_B 67584
#define GSM_BYTES 101376

__global__ __launch_bounds__(256, 2)
void gemm_T_kernel(const float* __restrict__ venue, int rows) {
    extern __shared__ __align__(16) char sm[];
    const int tid = threadIdx.x, lane = tid & 31, warp = tid >> 5;
    const int M0 = blockIdx.x * 128;
    const uint32_t smA = smem_u32(sm + GSM_A);
    const uint32_t smB = smem_u32(sm + GSM_B);

    // ---- issue B chunk 0 copy (overlaps normalize) ----
    {
        const char* src = reinterpret_cast<const char*>(g_Bt);
        #pragma unroll
        for (int s = 0; s < 8; ++s) {
            const int i = tid + s * 256;            // 0..2047
            const int row = i >> 5, j = i & 31;
            cp16(smB + row * ROWB + j * 16, src + row * 512 + j * 16);
        }
        cp_commit();
    }

    // ---- normalize 128 venue rows -> bf16 -> g_vnorm + smem A ----
    #pragma unroll
    for (int i = 0; i < 16; ++i) {
        const int lr  = warp * 16 + i;
        const int row = M0 + lr;
        if (row < rows) {
            const float4* src = reinterpret_cast<const float4*>(venue + (size_t)row * DIM) + lane * 2;
            float4 x0 = src[0], x1 = src[1];
            float ss = x0.x*x0.x + x0.y*x0.y + x0.z*x0.z + x0.w*x0.w
                     + x1.x*x1.x + x1.y*x1.y + x1.z*x1.z + x1.w*x1.w;
            #pragma unroll
            for (int o = 16; o > 0; o >>= 1) ss += __shfl_xor_sync(0xffffffffu, ss, o);
            const float sc = fminf(1.0f, 1.0f / fmaxf(sqrtf(ss), EPSF));   // torch max_norm=1
            __nv_bfloat162 b0 = __floats2bfloat162_rn(x0.x*sc, x0.y*sc);
            __nv_bfloat162 b1 = __floats2bfloat162_rn(x0.z*sc, x0.w*sc);
            __nv_bfloat162 b2 = __floats2bfloat162_rn(x1.x*sc, x1.y*sc);
            __nv_bfloat162 b3 = __floats2bfloat162_rn(x1.z*sc, x1.w*sc);
            uint4 o4;
            o4.x = *reinterpret_cast<uint32_t*>(&b0); o4.y = *reinterpret_cast<uint32_t*>(&b1);
            o4.z = *reinterpret_cast<uint32_t*>(&b2); o4.w = *reinterpret_cast<uint32_t*>(&b3);
            reinterpret_cast<uint4*>(g_vnorm + (size_t)row * DIM)[lane] = o4;
            *reinterpret_cast<uint4*>(sm + GSM_A + lr * ROWB + lane * 16) = o4;
        } else {
            *reinterpret_cast<uint4*>(sm + GSM_A + lr * ROWB + lane * 16) = make_uint4(0,0,0,0);
        }
    }

    // warp tile 32x32: mgrp = warp>>1 (rows), ngrp = warp&1 (cols within 64-chunk)
    const int qr = lane >> 2, qc = lane & 3;
    const int mgrp = warp >> 1, ngrp = warp & 1;
    const uint32_t aAddr = smA + (uint32_t)((mgrp * 32 + (lane & 15)) * ROWB + (lane >> 4) * 16);
    const uint32_t bAddr = smB + (uint32_t)((ngrp * 32 + (lane & 7) + ((lane >> 4) & 1) * 8) * ROWB
                                            + ((lane >> 3) & 1) * 16);

    #pragma unroll 1
    for (int chunk = 0; chunk < 4; ++chunk) {
        cp_wait0();
        __syncthreads();       // B chunk resident; A staged (chunk 0)

        float acc[2][4][4];
        #pragma unroll
        for (int mt = 0; mt < 2; ++mt)
            #pragma unroll
            for (int nt = 0; nt < 4; ++nt)
                #pragma unroll
                for (int i = 0; i < 4; ++i) acc[mt][nt][i] = 0.f;

        #pragma unroll 4
        for (int ks = 0; ks < 16; ++ks) {
            uint32_t af[2][4], bf[2][4];
            ldsm_x4(af[0], aAddr + ks * 32);
            ldsm_x4(af[1], aAddr + 16 * ROWB + ks * 32);
            ldsm_x4(bf[0], bAddr + ks * 32);
            ldsm_x4(bf[1], bAddr + 16 * ROWB + ks * 32);
            #pragma unroll
            for (int mt = 0; mt < 2; ++mt)
                #pragma unroll
                for (int nt = 0; nt < 4; ++nt)
                    mma_bf16(acc[mt][nt], af[mt],
                             bf[nt >> 1][(nt & 1) * 2], bf[nt >> 1][(nt & 1) * 2 + 1]);
        }
        __syncthreads();       // all warps done with B before refill

        if (chunk < 3) {
            const char* src = reinterpret_cast<const char*>(g_Bt + (chunk + 1) * 64 * DIM);
            #pragma unroll
            for (int s = 0; s < 8; ++s) {
                const int i = tid + s * 256;
                const int row = i >> 5, j = i & 31;
                cp16(smB + row * ROWB + j * 16, src + row * 512 + j * 16);
            }
            cp_commit();
        }

        // ---- store acc to g_T (fp32) ----
        #pragma unroll
        for (int mt = 0; mt < 2; ++mt) {
            #pragma unroll
            for (int nt = 0; nt < 4; ++nt) {
                const int col = chunk * 64 + ngrp * 32 + nt * 8 + 2 * qc;
                const int r0 = M0 + mgrp * 32 + mt * 16 + qr;
                if (r0 < rows)
                    *reinterpret_cast<float2*>(g_T + (size_t)r0 * DIM + col) =
                        make_float2(acc[mt][nt][0], acc[mt][nt][1]);
                if (r0 + 8 < rows)
                    *reinterpret_cast<float2*>(g_T + (size_t)(r0 + 8) * DIM + col) =
                        make_float2(acc[mt][nt][2], acc[mt][nt][3]);
            }
        }
    }
}

// ---------------- main kernel: gather + MUFU + reduce (no GEMM) ----------------
__global__ __launch_bounds__(256)
void geo_main_kernel(const int* __restrict__ batch_u,
                     const int* __restrict__ batch_v,
                     const int* __restrict__ batch_history,
                     const float* __restrict__ user_emb,
                     const float* __restrict__ venue_emb,
                     const float* __restrict__ a_ptr,
                     float* __restrict__ out) {
    __shared__ int   sidx[HIST];
    __shared__ float sred[24];
    __shared__ float sbc[3];

    const int b = blockIdx.x, tid = threadIdx.x, lane = tid & 31, warp = tid >> 5;
    if (tid < HIST) sidx[tid] = batch_history[b * HIST + tid];
    __syncthreads();

    const int d = tid;
    float den = 0.f, num = 0.f;

    #pragma unroll 1
    for (int rb = 0; rb < HIST; rb += 8) {
        #pragma unroll
        for (int i = 0; i < 8; ++i) {
            const int r = rb + i;
            const size_t off = (size_t)sidx[r] * DIM + d;
            const float t  = __ldg(g_T + off);
            const float c  = __ldg(g_C + r * DIM + d);
            const float hv = __bfloat162float(g_vnorm[off]);
            const float e  = __expf(tanh_fast(t + c));
            den += e;
            num = fmaf(e, hv, num);
        }
    }

    // ---- l = num/den + a; score = || l2n(u) + l2n(l) - l2n(v) || ----
    const float a_val = a_ptr[0];
    const float lv  = num / den + a_val;
    const float uvv = user_emb [(size_t)batch_u[b] * DIM + d];
    const float vvv = venue_emb[(size_t)batch_v[b] * DIM + d];
    float su = uvv * uvv, sv = vvv * vvv, sl = lv * lv;
    #pragma unroll
    for (int o = 16; o > 0; o >>= 1) {
        su += __shfl_xor_sync(0xffffffffu, su, o);
        sv += __shfl_xor_sync(0xffffffffu, sv, o);
        sl += __shfl_xor_sync(0xffffffffu, sl, o);
    }
    if (lane == 0) { sred[warp] = su; sred[8 + warp] = sv; sred[16 + warp] = sl; }
    __syncthreads();
    if (tid == 0) {
        float tu = 0.f, tv = 0.f, tl = 0.f;
        #pragma unroll
        for (int w = 0; w < 8; ++w) { tu += sred[w]; tv += sred[8 + w]; tl += sred[16 + w]; }
        sbc[0] = 1.f / fmaxf(sqrtf(tu), EPSF);
        sbc[1] = 1.f / fmaxf(sqrtf(tv), EPSF);
        sbc[2] = 1.f / fmaxf(sqrtf(tl), EPSF);
    }
    __syncthreads();
    float s = uvv * sbc[0] + lv * sbc[2] - vvv * sbc[1];
    float ssq = s * s;
    #pragma unroll
    for (int o = 16; o > 0; o >>= 1) ssq += __shfl_xor_sync(0xffffffffu, ssq, o);
    if (lane == 0) sred[warp] = ssq;
    __syncthreads();
    if (tid == 0) {
        float tot = 0.f;
        #pragma unroll
        for (int w = 0; w < 8; ++w) tot += sred[w];
        out[b] = sqrtf(tot);
    }
}

// ---------------- harness entry ----------------
extern "C" void kernel_launch(void* const* d_in, const int* in_sizes, int n_in,
                              void* d_out, int out_size) {
    const int*   batch_u       = (const int*)d_in[0];
    const int*   batch_v       = (const int*)d_in[1];
    const int*   batch_history = (const int*)d_in[2];
    const float* user_emb      = (const float*)d_in[5];
    const float* venue_emb     = (const float*)d_in[6];
    const float* W1            = (const float*)d_in[7];
    const float* W2            = (const float*)d_in[8];
    const float* P             = (const float*)d_in[9];
    const float* bias          = (const float*)d_in[10];
    const float* a             = (const float*)d_in[11];
    float* out = (float*)d_out;

    const int B = in_sizes[0];
    int rows = in_sizes[6] / DIM;
    if (rows > VROWS) rows = VROWS;

    cudaFuncSetAttribute(gemm_T_kernel,
                         cudaFuncAttributeMaxDynamicSharedMemorySize, GSM_BYTES);

    build_Bt_kernel<<<DIM, DIM>>>(W1);
    compute_C_kernel<<<HIST, DIM>>>(P, W2, bias);
    gemm_T_kernel<<<(rows + 127) / 128, 256, GSM_BYTES>>>(venue_emb, rows);
    geo_main_kernel<<<B, 256>>>(batch_u, batch_v, batch_history,
                                user_emb, venue_emb, a, out);
}

// round 6
// speedup vs baseline: 8.3287x; 1.2175x over previous
#include <cuda_runtime.h>
#include <cuda_bf16.h>
#include <cstdint>

#define DIM   256
#define HIST  200
#define VROWS 100000
#define EPSF  1e-12f
#define ROWB  528            // smem row stride bytes: (256+8) bf16

// ---------------- persistent device scratch ----------------
__device__ __nv_bfloat16 g_Bt[DIM * DIM];          // W1^T  (Bt[n][k] = W1[k][n])
__device__ float         g_C[HIST * DIM];          // P@W2 + bias
__device__ uint32_t      g_TV[(size_t)VROWS * DIM]; // packed: lo16=T bf16, hi16=vnorm bf16

// ---------------- helpers ----------------
__device__ __forceinline__ uint32_t smem_u32(const void* p) {
    uint32_t a;
    asm("{ .reg .u64 t; cvta.to.shared.u64 t, %1; cvt.u32.u64 %0, t; }" : "=r"(a) : "l"(p));
    return a;
}
__device__ __forceinline__ float tanh_fast(float x) {
    float y; asm("tanh.approx.f32 %0, %1;" : "=f"(y) : "f"(x)); return y;
}
__device__ __forceinline__ void ldsm_x4(uint32_t* r, uint32_t addr) {
    asm volatile("ldmatrix.sync.aligned.m8n8.x4.shared.b16 {%0,%1,%2,%3}, [%4];"
                 : "=r"(r[0]), "=r"(r[1]), "=r"(r[2]), "=r"(r[3]) : "r"(addr));
}
__device__ __forceinline__ void mma_bf16(float* d, const uint32_t* a,
                                         uint32_t b0, uint32_t b1) {
    asm volatile(
        "mma.sync.aligned.m16n8k16.row.col.f32.bf16.bf16.f32 "
        "{%0,%1,%2,%3}, {%4,%5,%6,%7}, {%8,%9}, {%0,%1,%2,%3};"
        : "+f"(d[0]), "+f"(d[1]), "+f"(d[2]), "+f"(d[3])
        : "r"(a[0]), "r"(a[1]), "r"(a[2]), "r"(a[3]), "r"(b0), "r"(b1));
}
__device__ __forceinline__ void cp16(uint32_t dst, const void* src) {
    asm volatile("cp.async.cg.shared.global [%0], [%1], 16;" :: "r"(dst), "l"(src));
}
__device__ __forceinline__ void cp_commit() { asm volatile("cp.async.commit_group;" ::: "memory"); }
__device__ __forceinline__ void cp_wait0()  { asm volatile("cp.async.wait_group 0;" ::: "memory"); }

// ---------------- small precompute kernels ----------------
__global__ void build_Bt_kernel(const float* __restrict__ W1) {
    const int n = blockIdx.x, k = threadIdx.x;
    g_Bt[n * DIM + k] = __float2bfloat16(W1[k * DIM + n]);
}

__global__ void compute_C_kernel(const float* __restrict__ P,
                                 const float* __restrict__ W2,
                                 const float* __restrict__ bias) {
    __shared__ float sP[DIM];
    const int h = blockIdx.x, d = threadIdx.x;
    sP[d] = P[h * DIM + d];
    __syncthreads();
    float acc = 0.f;
    #pragma unroll 16
    for (int k = 0; k < DIM; ++k) acc = fmaf(sP[k], W2[k * DIM + d], acc);
    g_C[h * DIM + d] = acc + bias[h * DIM + d];
}

// ---------------- TV = pack(max_norm(venue) @ W1, max_norm(venue)) ----------------
// grid = ceil(rows/128), 256 threads, smem A 67584 + B 33792 = 101376 -> occ 2
#define GSM_A 0
#define GSM_B 67584
#define GSM_BYTES 101376

__global__ __launch_bounds__(256, 2)
void gemm_T_kernel(const float* __restrict__ venue, int rows) {
    extern __shared__ __align__(16) char sm[];
    const int tid = threadIdx.x, lane = tid & 31, warp = tid >> 5;
    const int M0 = blockIdx.x * 128;
    const uint32_t smA = smem_u32(sm + GSM_A);
    const uint32_t smB = smem_u32(sm + GSM_B);

    // ---- issue B chunk 0 copy (overlaps normalize) ----
    {
        const char* src = reinterpret_cast<const char*>(g_Bt);
        #pragma unroll
        for (int s = 0; s < 8; ++s) {
            const int i = tid + s * 256;            // 0..2047
            const int row = i >> 5, j = i & 31;
            cp16(smB + row * ROWB + j * 16, src + row * 512 + j * 16);
        }
        cp_commit();
    }

    // ---- normalize 128 venue rows -> bf16 -> smem A ----
    #pragma unroll
    for (int i = 0; i < 16; ++i) {
        const int lr  = warp * 16 + i;
        const int row = M0 + lr;
        if (row < rows) {
            const float4* src = reinterpret_cast<const float4*>(venue + (size_t)row * DIM) + lane * 2;
            float4 x0 = src[0], x1 = src[1];
            float ss = x0.x*x0.x + x0.y*x0.y + x0.z*x0.z + x0.w*x0.w
                     + x1.x*x1.x + x1.y*x1.y + x1.z*x1.z + x1.w*x1.w;
            #pragma unroll
            for (int o = 16; o > 0; o >>= 1) ss += __shfl_xor_sync(0xffffffffu, ss, o);
            const float sc = fminf(1.0f, 1.0f / fmaxf(sqrtf(ss), EPSF));   // torch max_norm=1
            __nv_bfloat162 b0 = __floats2bfloat162_rn(x0.x*sc, x0.y*sc);
            __nv_bfloat162 b1 = __floats2bfloat162_rn(x0.z*sc, x0.w*sc);
            __nv_bfloat162 b2 = __floats2bfloat162_rn(x1.x*sc, x1.y*sc);
            __nv_bfloat162 b3 = __floats2bfloat162_rn(x1.z*sc, x1.w*sc);
            uint4 o4;
            o4.x = *reinterpret_cast<uint32_t*>(&b0); o4.y = *reinterpret_cast<uint32_t*>(&b1);
            o4.z = *reinterpret_cast<uint32_t*>(&b2); o4.w = *reinterpret_cast<uint32_t*>(&b3);
            *reinterpret_cast<uint4*>(sm + GSM_A + lr * ROWB + lane * 16) = o4;
        } else {
            *reinterpret_cast<uint4*>(sm + GSM_A + lr * ROWB + lane * 16) = make_uint4(0,0,0,0);
        }
    }

    // warp tile 32x32: mgrp = warp>>1 (rows), ngrp = warp&1 (cols within 64-chunk)
    const int qr = lane >> 2, qc = lane & 3;
    const int mgrp = warp >> 1, ngrp = warp & 1;
    const uint32_t aAddr = smA + (uint32_t)((mgrp * 32 + (lane & 15)) * ROWB + (lane >> 4) * 16);
    const uint32_t bAddr = smB + (uint32_t)((ngrp * 32 + (lane & 7) + ((lane >> 4) & 1) * 8) * ROWB
                                            + ((lane >> 3) & 1) * 16);

    #pragma unroll 1
    for (int chunk = 0; chunk < 4; ++chunk) {
        cp_wait0();
        __syncthreads();       // B chunk resident; A staged (chunk 0)

        float acc[2][4][4];
        #pragma unroll
        for (int mt = 0; mt < 2; ++mt)
            #pragma unroll
            for (int nt = 0; nt < 4; ++nt)
                #pragma unroll
                for (int i = 0; i < 4; ++i) acc[mt][nt][i] = 0.f;

        #pragma unroll 4
        for (int ks = 0; ks < 16; ++ks) {
            uint32_t af[2][4], bf[2][4];
            ldsm_x4(af[0], aAddr + ks * 32);
            ldsm_x4(af[1], aAddr + 16 * ROWB + ks * 32);
            ldsm_x4(bf[0], bAddr + ks * 32);
            ldsm_x4(bf[1], bAddr + 16 * ROWB + ks * 32);
            #pragma unroll
            for (int mt = 0; mt < 2; ++mt)
                #pragma unroll
                for (int nt = 0; nt < 4; ++nt)
                    mma_bf16(acc[mt][nt], af[mt],
                             bf[nt >> 1][(nt & 1) * 2], bf[nt >> 1][(nt & 1) * 2 + 1]);
        }
        __syncthreads();       // all warps done with B before refill

        if (chunk < 3) {
            const char* src = reinterpret_cast<const char*>(g_Bt + (chunk + 1) * 64 * DIM);
            #pragma unroll
            for (int s = 0; s < 8; ++s) {
                const int i = tid + s * 256;
                const int row = i >> 5, j = i & 31;
                cp16(smB + row * ROWB + j * 16, src + row * 512 + j * 16);
            }
            cp_commit();
        }

        // ---- pack T(bf16) + vnorm(bf16) -> g_TV (uint32/elem) ----
        #pragma unroll
        for (int mt = 0; mt < 2; ++mt) {
            const int lr0 = mgrp * 32 + mt * 16 + qr;
            #pragma unroll
            for (int nt = 0; nt < 4; ++nt) {
                const int col = chunk * 64 + ngrp * 32 + nt * 8 + 2 * qc;
                #pragma unroll
                for (int half = 0; half < 2; ++half) {
                    const int r0 = M0 + lr0 + half * 8;
                    if (r0 < rows) {
                        // vnorm pair from smem A (row staged earlier, still valid)
                        const uint32_t hh = *reinterpret_cast<const uint32_t*>(
                            sm + GSM_A + (lr0 + half * 8) * ROWB + col * 2);
                        __nv_bfloat162 tp = __floats2bfloat162_rn(
                            acc[mt][nt][half * 2 + 0], acc[mt][nt][half * 2 + 1]);
                        const uint32_t tpu = *reinterpret_cast<uint32_t*>(&tp);
                        uint2 st;
                        st.x = __byte_perm(tpu, hh, 0x5410);   // {T_lo, v_lo}
                        st.y = __byte_perm(tpu, hh, 0x7632);   // {T_hi, v_hi}
                        *reinterpret_cast<uint2*>(g_TV + (size_t)r0 * DIM + col) = st;
                    }
                }
            }
        }
    }
}

// ---------------- main kernel: gather + MUFU + reduce (no GEMM) ----------------
__global__ __launch_bounds__(256)
void geo_main_kernel(const int* __restrict__ batch_u,
                     const int* __restrict__ batch_v,
                     const int* __restrict__ batch_history,
                     const float* __restrict__ user_emb,
                     const float* __restrict__ venue_emb,
                     const float* __restrict__ a_ptr,
                     float* __restrict__ out) {
    __shared__ int   sidx[HIST];
    __shared__ float sred[24];
    __shared__ float sbc[3];

    const int b = blockIdx.x, tid = threadIdx.x, lane = tid & 31, warp = tid >> 5;
    if (tid < HIST) sidx[tid] = batch_history[b * HIST + tid];
    __syncthreads();

    const int d = tid;
    float den = 0.f, num = 0.f;
    const float* Cd = g_C + d;

    #pragma unroll 1
    for (int rb = 0; rb < HIST; rb += 8) {
        #pragma unroll
        for (int i = 0; i < 8; ++i) {
            const int r = rb + i;
            const uint32_t off = ((uint32_t)sidx[r] << 8) + d;
            const uint32_t tv  = __ldg(g_TV + off);
            const float c  = __ldg(Cd + r * DIM);
            const float t  = __uint_as_float(tv << 16);           // bf16 lo -> f32
            const float hv = __uint_as_float(tv & 0xffff0000u);   // bf16 hi -> f32
            const float e  = __expf(tanh_fast(t + c));
            den += e;
            num = fmaf(e, hv, num);
        }
    }

    // ---- l = num/den + a; score = || l2n(u) + l2n(l) - l2n(v) || ----
    const float a_val = a_ptr[0];
    const float lv  = num / den + a_val;
    const float uvv = user_emb [(size_t)batch_u[b] * DIM + d];
    const float vvv = venue_emb[(size_t)batch_v[b] * DIM + d];
    float su = uvv * uvv, sv = vvv * vvv, sl = lv * lv;
    #pragma unroll
    for (int o = 16; o > 0; o >>= 1) {
        su += __shfl_xor_sync(0xffffffffu, su, o);
        sv += __shfl_xor_sync(0xffffffffu, sv, o);
        sl += __shfl_xor_sync(0xffffffffu, sl, o);
    }
    if (lane == 0) { sred[warp] = su; sred[8 + warp] = sv; sred[16 + warp] = sl; }
    __syncthreads();
    if (tid == 0) {
        float tu = 0.f, tv2 = 0.f, tl = 0.f;
        #pragma unroll
        for (int w = 0; w < 8; ++w) { tu += sred[w]; tv2 += sred[8 + w]; tl += sred[16 + w]; }
        sbc[0] = 1.f / fmaxf(sqrtf(tu), EPSF);
        sbc[1] = 1.f / fmaxf(sqrtf(tv2), EPSF);
        sbc[2] = 1.f / fmaxf(sqrtf(tl), EPSF);
    }
    __syncthreads();
    float s = uvv * sbc[0] + lv * sbc[2] - vvv * sbc[1];
    float ssq = s * s;
    #pragma unroll
    for (int o = 16; o > 0; o >>= 1) ssq += __shfl_xor_sync(0xffffffffu, ssq, o);
    if (lane == 0) sred[warp] = ssq;
    __syncthreads();
    if (tid == 0) {
        float tot = 0.f;
        #pragma unroll
        for (int w = 0; w < 8; ++w) tot += sred[w];
        out[b] = sqrtf(tot);
    }
}

// ---------------- harness entry ----------------
extern "C" void kernel_launch(void* const* d_in, const int* in_sizes, int n_in,
                              void* d_out, int out_size) {
    const int*   batch_u       = (const int*)d_in[0];
    const int*   batch_v       = (const int*)d_in[1];
    const int*   batch_history = (const int*)d_in[2];
    const float* user_emb      = (const float*)d_in[5];
    const float* venue_emb     = (const float*)d_in[6];
    const float* W1            = (const float*)d_in[7];
    const float* W2            = (const float*)d_in[8];
    const float* P             = (const float*)d_in[9];
    const float* bias          = (const float*)d_in[10];
    const float* a             = (const float*)d_in[11];
    float* out = (float*)d_out;

    const int B = in_sizes[0];
    int rows = in_sizes[6] / DIM;
    if (rows > VROWS) rows = VROWS;

    cudaFuncSetAttribute(gemm_T_kernel,
                         cudaFuncAttributeMaxDynamicSharedMemorySize, GSM_BYTES);

    build_Bt_kernel<<<DIM, DIM>>>(W1);
    compute_C_kernel<<<HIST, DIM>>>(P, W2, bias);
    gemm_T_kernel<<<(rows + 127) / 128, 256, GSM_BYTES>>>(venue_emb, rows);
    geo_main_kernel<<<B, 256>>>(batch_u, batch_v, batch_history,
                                user_emb, venue_emb, a, out);
}